// round 1
// baseline (speedup 1.0000x reference)
#include <cuda_runtime.h>
#include <cuda_bf16.h>

// ---------------------------------------------------------------------------
// TDSPMLPHead: out[b,n,m] = (silu(LN(cat(t,d,|t-d|) @ W1 + b1)) @ W2 + b2)
// Decomposition: h = tA[b,n,:] + dD[b,m,:] + |t-d| @ W1c
//   tA = t_norm @ W1[0:256,:]          (precomputed, exact fp32)
//   dD = d_norm @ W1[256:512,:] + b1   (precomputed, exact fp32)
//   pairwise term: 64x512x256 fp32 GEMM per CTA via fma.rn.f32x2
// ---------------------------------------------------------------------------

#define Bn 8
#define Nn 128
#define Mn 128
#define En 256
#define Hn 512
#define NROWS (Bn*Nn)            // 1024 (== Bn*Mn)

__device__ float g_tn[NROWS*En];
__device__ float g_dn[NROWS*En];
__device__ float g_tA[NROWS*Hn];
__device__ float g_dD[NROWS*Hn];

// ---- packed f32x2 helpers (sm_100+) ----
__device__ __forceinline__ unsigned long long pack2(float lo, float hi) {
    unsigned long long r;
    asm("mov.b64 %0, {%1, %2};" : "=l"(r) : "f"(lo), "f"(hi));
    return r;
}
__device__ __forceinline__ void unpack2(unsigned long long v, float& x, float& y) {
    asm("mov.b64 {%0, %1}, %2;" : "=f"(x), "=f"(y) : "l"(v));
}
__device__ __forceinline__ unsigned long long fma2(unsigned long long a,
                                                   unsigned long long b,
                                                   unsigned long long c) {
    unsigned long long d;
    asm("fma.rn.f32x2 %0, %1, %2, %3;" : "=l"(d) : "l"(a), "l"(b), "l"(c));
    return d;
}
__device__ __forceinline__ float sigmoid_fast(float x) {
    float t;
    asm("tanh.approx.f32 %0, %1;" : "=f"(t) : "f"(x * 0.5f));
    return 0.5f * t + 0.5f;
}

// ---------------------------------------------------------------------------
// Kernel 1: normalize rows + small exact GEMMs (tA, dD). 16 rows per CTA.
// grid = 2*NROWS/16 = 128 blocks, 256 threads.
// ---------------------------------------------------------------------------
__global__ __launch_bounds__(256) void prep_kernel(
    const float* __restrict__ track, const float* __restrict__ det,
    const float* __restrict__ W1, const float* __restrict__ b1)
{
    __shared__ float sX[16][En];
    __shared__ float sScale[16];
    const int tid = threadIdx.x;
    const int rb  = blockIdx.x * 16;            // global row base (0..2047)
    const bool isT = (rb < NROWS);
    const float* src = isT ? (track + rb * En) : (det + (rb - NROWS) * En);

    for (int idx = tid; idx < 16 * En; idx += 256)
        sX[idx >> 8][idx & 255] = src[idx];
    __syncthreads();

    {   // per-row 1/max(||x||, 1e-12): row = tid>>4, 16 lanes per row
        const int row = tid >> 4, k = tid & 15;
        float ss = 0.f;
        #pragma unroll
        for (int i = 0; i < 16; i++) { float v = sX[row][k + 16 * i]; ss += v * v; }
        #pragma unroll
        for (int o = 8; o; o >>= 1) ss += __shfl_xor_sync(0xffffffffu, ss, o);
        if (k == 0) sScale[row] = 1.0f / fmaxf(sqrtf(ss), 1e-12f);
    }
    __syncthreads();

    float* gnorm = isT ? (g_tn + rb * En) : (g_dn + (rb - NROWS) * En);
    for (int idx = tid; idx < 16 * En; idx += 256) {
        const int row = idx >> 8, e = idx & 255;
        float v = sX[row][e] * sScale[row];
        sX[row][e] = v;
        gnorm[idx] = v;
    }
    __syncthreads();

    // GEMM: Y[16][512]; this thread owns columns {2*tid, 2*tid+1}
    const float* Wp = W1 + (isT ? 0 : En * Hn);
    unsigned long long acc[16];
    #pragma unroll
    for (int r = 0; r < 16; r++) acc[r] = 0ull;

    #pragma unroll 4
    for (int e = 0; e < En; e++) {
        const unsigned long long w =
            *(const unsigned long long*)(Wp + (size_t)e * Hn + 2 * tid);
        #pragma unroll
        for (int r = 0; r < 16; r++) {
            const float s = sX[r][e];
            acc[r] = fma2(pack2(s, s), w, acc[r]);
        }
    }

    float bx = 0.f, by = 0.f;
    if (!isT) { bx = b1[2 * tid]; by = b1[2 * tid + 1]; }
    float* yout = isT ? (g_tA + rb * Hn) : (g_dD + (rb - NROWS) * Hn);
    #pragma unroll
    for (int r = 0; r < 16; r++) {
        float x, y; unpack2(acc[r], x, y);
        float2 v; v.x = x + bx; v.y = y + by;
        *(float2*)(yout + (size_t)r * Hn + 2 * tid) = v;
    }
}

// ---------------------------------------------------------------------------
// Kernel 2: fused pairwise GEMM + LayerNorm + SiLU + W2 dot.
// CTA = one (b, n, m-half): 64 pairs x 512 h, K=256.
// 256 threads: im = tid>>4 (4 m-rows each), ih = tid&15 (h = 2*ih + 32*j).
// grid = 2048 blocks.
// ---------------------------------------------------------------------------
#define EC 64
#define DSTRIDE 257
#define SMEM_FLOATS (64*DSTRIDE + EC*Hn + En + Hn + Hn + Hn + Hn)
#define SMEM_BYTES  (SMEM_FLOATS * 4)

__global__ __launch_bounds__(256, 1) void main_kernel(
    const float* __restrict__ W1, const float* __restrict__ gamma,
    const float* __restrict__ beta, const float* __restrict__ W2,
    const float* __restrict__ b2, float* __restrict__ out)
{
    extern __shared__ float sm[];
    float* sDiff = sm;                        // [64][DSTRIDE]
    float* sW    = sDiff + 64 * DSTRIDE;      // [EC][512]  (offset 65792 B, 16B aligned)
    float* sTn   = sW + EC * Hn;              // [256]
    float* sTA   = sTn + En;                  // [512]
    float* sG    = sTA + Hn;                  // [512]
    float* sB    = sG + Hn;                   // [512]
    float* sW2g  = sB + Hn;                   // [512]

    const int tid = threadIdx.x;
    const int im = tid >> 4, ih = tid & 15;
    const int tile = blockIdx.x;
    const int pr = tile >> 1;                 // b*128 + n
    const int m0 = (tile & 1) * 64;
    const int b  = pr >> 7;

    // stage per-CTA constants
    const float* tn = g_tn + (size_t)pr * En;
    for (int i = tid; i < En; i += 256) sTn[i] = tn[i];
    for (int i = tid; i < Hn; i += 256) {
        sTA[i]  = g_tA[(size_t)pr * Hn + i];
        sG[i]   = gamma[i];
        sB[i]   = beta[i];
        sW2g[i] = W2[i];
    }
    __syncthreads();

    // |t - d| tile: rows m0..m0+63 of batch b, m-major
    const float* dn = g_dn + ((size_t)(b * Mn + m0)) * En;
    for (int idx = tid; idx < 64 * En; idx += 256) {
        const int m = idx >> 8, e = idx & 255;
        sDiff[m * DSTRIDE + e] = fabsf(sTn[e] - dn[idx]);
    }

    unsigned long long acc[4][16];
    #pragma unroll
    for (int a = 0; a < 4; a++)
        #pragma unroll
        for (int j = 0; j < 16; j++) acc[a][j] = 0ull;

    const float* W1c = W1 + (size_t)(2 * En) * Hn;   // rows [512, 768)
    for (int kc = 0; kc < En; kc += EC) {
        __syncthreads();   // diff ready (iter 0) / previous slab consumed
        const float4* src = (const float4*)(W1c + (size_t)kc * Hn);
        float4* dst = (float4*)sW;
        #pragma unroll
        for (int i = tid; i < EC * Hn / 4; i += 256) dst[i] = src[i];
        __syncthreads();

        for (int e = 0; e < EC; e++) {
            unsigned long long w[16];
            #pragma unroll
            for (int j = 0; j < 16; j++)
                w[j] = *(const unsigned long long*)(sW + e * Hn + 32 * j + 2 * ih);
            #pragma unroll
            for (int a = 0; a < 4; a++) {
                const float s = sDiff[(4 * im + a) * DSTRIDE + kc + e];
                const unsigned long long s2 = pack2(s, s);
                #pragma unroll
                for (int j = 0; j < 16; j++)
                    acc[a][j] = fma2(s2, w[j], acc[a][j]);
            }
        }
    }

    // fused epilogue: +tA +dD, LayerNorm over H, SiLU, dot W2
    const float* dD = g_dD + ((size_t)(b * Mn + m0)) * Hn;
    float outv[4];
    #pragma unroll
    for (int a = 0; a < 4; a++) {
        const int m = 4 * im + a;
        float sum = 0.f, ssq = 0.f;
        #pragma unroll
        for (int j = 0; j < 16; j++) {
            const int h = 32 * j + 2 * ih;
            float hx, hy; unpack2(acc[a][j], hx, hy);
            const float2 dd = *(const float2*)(dD + (size_t)m * Hn + h);
            hx += sTA[h]     + dd.x;
            hy += sTA[h + 1] + dd.y;
            acc[a][j] = pack2(hx, hy);
            sum += hx + hy;
            ssq += hx * hx + hy * hy;
        }
        #pragma unroll
        for (int o = 1; o < 16; o <<= 1) {
            sum += __shfl_xor_sync(0xffffffffu, sum, o);
            ssq += __shfl_xor_sync(0xffffffffu, ssq, o);
        }
        const float mu  = sum * (1.0f / 512.0f);
        const float var = ssq * (1.0f / 512.0f) - mu * mu;
        const float rs  = rsqrtf(var + 1e-5f);

        float dot = 0.f;
        #pragma unroll
        for (int j = 0; j < 16; j++) {
            const int h = 32 * j + 2 * ih;
            float hx, hy; unpack2(acc[a][j], hx, hy);
            const float yx = (hx - mu) * rs * sG[h]     + sB[h];
            const float yy = (hy - mu) * rs * sG[h + 1] + sB[h + 1];
            const float sx = yx * sigmoid_fast(yx);
            const float sy = yy * sigmoid_fast(yy);
            dot += sx * sW2g[h] + sy * sW2g[h + 1];
        }
        #pragma unroll
        for (int o = 1; o < 16; o <<= 1)
            dot += __shfl_xor_sync(0xffffffffu, dot, o);
        outv[a] = dot;
    }

    if (ih == 0) {
        const float bb = b2[0];
        float* o = out + (size_t)pr * Mn + m0 + 4 * im;
        #pragma unroll
        for (int a = 0; a < 4; a++) o[a] = outv[a] + bb;
    }
}

// ---------------------------------------------------------------------------
extern "C" void kernel_launch(void* const* d_in, const int* in_sizes, int n_in,
                              void* d_out, int out_size) {
    const float* track = (const float*)d_in[0];
    const float* det   = (const float*)d_in[1];
    const float* W1    = (const float*)d_in[2];
    const float* b1    = (const float*)d_in[3];
    const float* gamma = (const float*)d_in[4];
    const float* beta  = (const float*)d_in[5];
    const float* W2    = (const float*)d_in[6];
    const float* b2    = (const float*)d_in[7];
    float* out = (float*)d_out;

    cudaFuncSetAttribute(main_kernel,
                         cudaFuncAttributeMaxDynamicSharedMemorySize, SMEM_BYTES);

    prep_kernel<<<128, 256>>>(track, det, W1, b1);
    main_kernel<<<2 * Bn * Nn, 256, SMEM_BYTES>>>(W1, gamma, beta, W2, b2, out);
}

// round 2
// speedup vs baseline: 1.0011x; 1.0011x over previous
#include <cuda_runtime.h>
#include <cuda_bf16.h>

// ---------------------------------------------------------------------------
// TDSPMLPHead: out[b,n,m] = (silu(LN(cat(t,d,|t-d|) @ W1 + b1)) @ W2 + b2)
// Decomposition: h = tA[b,n,:] + dD[b,m,:] + |t-d| @ W1c
//   tA = t_norm @ W1[0:256,:]          (precomputed, exact fp32)
//   dD = d_norm @ W1[256:512,:] + b1   (precomputed, exact fp32)
//   pairwise term: 64x512x256 fp32 GEMM per CTA via fma.rn.f32x2
// ---------------------------------------------------------------------------

#define Bn 8
#define Nn 128
#define Mn 128
#define En 256
#define Hn 512
#define NROWS (Bn*Nn)            // 1024 (== Bn*Mn)

__device__ float g_tn[NROWS*En];
__device__ float g_dn[NROWS*En];
__device__ float g_tA[NROWS*Hn];
__device__ float g_dD[NROWS*Hn];

// ---- packed f32x2 helpers (sm_100+) ----
__device__ __forceinline__ unsigned long long pack2(float lo, float hi) {
    unsigned long long r;
    asm("mov.b64 %0, {%1, %2};" : "=l"(r) : "f"(lo), "f"(hi));
    return r;
}
__device__ __forceinline__ void unpack2(unsigned long long v, float& x, float& y) {
    asm("mov.b64 {%0, %1}, %2;" : "=f"(x), "=f"(y) : "l"(v));
}
__device__ __forceinline__ unsigned long long fma2(unsigned long long a,
                                                   unsigned long long b,
                                                   unsigned long long c) {
    unsigned long long d;
    asm("fma.rn.f32x2 %0, %1, %2, %3;" : "=l"(d) : "l"(a), "l"(b), "l"(c));
    return d;
}
__device__ __forceinline__ float sigmoid_fast(float x) {
    float t;
    asm("tanh.approx.f32 %0, %1;" : "=f"(t) : "f"(x * 0.5f));
    return 0.5f * t + 0.5f;
}

// ---------------------------------------------------------------------------
// Kernel 1: normalize rows + small exact GEMMs (tA, dD). 16 rows per CTA.
// grid = 2*NROWS/16 = 128 blocks, 256 threads.
// ---------------------------------------------------------------------------
__global__ __launch_bounds__(256) void prep_kernel(
    const float* __restrict__ track, const float* __restrict__ det,
    const float* __restrict__ W1, const float* __restrict__ b1)
{
    __shared__ float sX[16][En];
    __shared__ float sScale[16];
    const int tid = threadIdx.x;
    const int rb  = blockIdx.x * 16;            // global row base (0..2047)
    const bool isT = (rb < NROWS);
    const float* src = isT ? (track + rb * En) : (det + (rb - NROWS) * En);

    for (int idx = tid; idx < 16 * En; idx += 256)
        sX[idx >> 8][idx & 255] = src[idx];
    __syncthreads();

    {   // per-row 1/max(||x||, 1e-12): row = tid>>4, 16 lanes per row
        const int row = tid >> 4, k = tid & 15;
        float ss = 0.f;
        #pragma unroll
        for (int i = 0; i < 16; i++) { float v = sX[row][k + 16 * i]; ss += v * v; }
        #pragma unroll
        for (int o = 8; o; o >>= 1) ss += __shfl_xor_sync(0xffffffffu, ss, o);
        if (k == 0) sScale[row] = 1.0f / fmaxf(sqrtf(ss), 1e-12f);
    }
    __syncthreads();

    float* gnorm = isT ? (g_tn + rb * En) : (g_dn + (rb - NROWS) * En);
    for (int idx = tid; idx < 16 * En; idx += 256) {
        const int row = idx >> 8, e = idx & 255;
        float v = sX[row][e] * sScale[row];
        sX[row][e] = v;
        gnorm[idx] = v;
    }
    __syncthreads();

    // GEMM: Y[16][512]; this thread owns columns {2*tid, 2*tid+1}
    const float* Wp = W1 + (isT ? 0 : En * Hn);
    unsigned long long acc[16];
    #pragma unroll
    for (int r = 0; r < 16; r++) acc[r] = 0ull;

    #pragma unroll 4
    for (int e = 0; e < En; e++) {
        const unsigned long long w =
            *(const unsigned long long*)(Wp + (size_t)e * Hn + 2 * tid);
        #pragma unroll
        for (int r = 0; r < 16; r++) {
            const float s = sX[r][e];
            acc[r] = fma2(pack2(s, s), w, acc[r]);
        }
    }

    float bx = 0.f, by = 0.f;
    if (!isT) { bx = b1[2 * tid]; by = b1[2 * tid + 1]; }
    float* yout = isT ? (g_tA + rb * Hn) : (g_dD + (rb - NROWS) * Hn);
    #pragma unroll
    for (int r = 0; r < 16; r++) {
        float x, y; unpack2(acc[r], x, y);
        float2 v; v.x = x + bx; v.y = y + by;
        *(float2*)(yout + (size_t)r * Hn + 2 * tid) = v;
    }
}

// ---------------------------------------------------------------------------
// Kernel 2: fused pairwise GEMM + LayerNorm + SiLU + W2 dot.
// CTA = one (b, n, m-half): 64 pairs x 512 h, K=256.
// 256 threads: im = tid>>4 (4 m-rows each), ih = tid&15 (h = 2*ih + 32*j).
// grid = 2048 blocks.
// ---------------------------------------------------------------------------
#define EC 64
#define DSTRIDE 257
#define SMEM_FLOATS (64*DSTRIDE + EC*Hn + En + Hn + Hn + Hn + Hn)
#define SMEM_BYTES  (SMEM_FLOATS * 4)

__global__ __launch_bounds__(256, 1) void main_kernel(
    const float* __restrict__ W1, const float* __restrict__ gamma,
    const float* __restrict__ beta, const float* __restrict__ W2,
    const float* __restrict__ b2, float* __restrict__ out)
{
    extern __shared__ float sm[];
    float* sDiff = sm;                        // [64][DSTRIDE]
    float* sW    = sDiff + 64 * DSTRIDE;      // [EC][512]  (offset 65792 B, 16B aligned)
    float* sTn   = sW + EC * Hn;              // [256]
    float* sTA   = sTn + En;                  // [512]
    float* sG    = sTA + Hn;                  // [512]
    float* sB    = sG + Hn;                   // [512]
    float* sW2g  = sB + Hn;                   // [512]

    const int tid = threadIdx.x;
    const int im = tid >> 4, ih = tid & 15;
    const int tile = blockIdx.x;
    const int pr = tile >> 1;                 // b*128 + n
    const int m0 = (tile & 1) * 64;
    const int b  = pr >> 7;

    // stage per-CTA constants
    const float* tn = g_tn + (size_t)pr * En;
    for (int i = tid; i < En; i += 256) sTn[i] = tn[i];
    for (int i = tid; i < Hn; i += 256) {
        sTA[i]  = g_tA[(size_t)pr * Hn + i];
        sG[i]   = gamma[i];
        sB[i]   = beta[i];
        sW2g[i] = W2[i];
    }
    __syncthreads();

    // |t - d| tile: rows m0..m0+63 of batch b, m-major
    const float* dn = g_dn + ((size_t)(b * Mn + m0)) * En;
    for (int idx = tid; idx < 64 * En; idx += 256) {
        const int m = idx >> 8, e = idx & 255;
        sDiff[m * DSTRIDE + e] = fabsf(sTn[e] - dn[idx]);
    }

    unsigned long long acc[4][16];
    #pragma unroll
    for (int a = 0; a < 4; a++)
        #pragma unroll
        for (int j = 0; j < 16; j++) acc[a][j] = 0ull;

    const float* W1c = W1 + (size_t)(2 * En) * Hn;   // rows [512, 768)
    for (int kc = 0; kc < En; kc += EC) {
        __syncthreads();   // diff ready (iter 0) / previous slab consumed
        const float4* src = (const float4*)(W1c + (size_t)kc * Hn);
        float4* dst = (float4*)sW;
        #pragma unroll
        for (int i = tid; i < EC * Hn / 4; i += 256) dst[i] = src[i];
        __syncthreads();

        for (int e = 0; e < EC; e++) {
            unsigned long long w[16];
            #pragma unroll
            for (int j = 0; j < 16; j++)
                w[j] = *(const unsigned long long*)(sW + e * Hn + 32 * j + 2 * ih);
            #pragma unroll
            for (int a = 0; a < 4; a++) {
                const float s = sDiff[(4 * im + a) * DSTRIDE + kc + e];
                const unsigned long long s2 = pack2(s, s);
                #pragma unroll
                for (int j = 0; j < 16; j++)
                    acc[a][j] = fma2(s2, w[j], acc[a][j]);
            }
        }
    }

    // fused epilogue: +tA +dD, LayerNorm over H, SiLU, dot W2
    const float* dD = g_dD + ((size_t)(b * Mn + m0)) * Hn;
    float outv[4];
    #pragma unroll
    for (int a = 0; a < 4; a++) {
        const int m = 4 * im + a;
        float sum = 0.f, ssq = 0.f;
        #pragma unroll
        for (int j = 0; j < 16; j++) {
            const int h = 32 * j + 2 * ih;
            float hx, hy; unpack2(acc[a][j], hx, hy);
            const float2 dd = *(const float2*)(dD + (size_t)m * Hn + h);
            hx += sTA[h]     + dd.x;
            hy += sTA[h + 1] + dd.y;
            acc[a][j] = pack2(hx, hy);
            sum += hx + hy;
            ssq += hx * hx + hy * hy;
        }
        #pragma unroll
        for (int o = 1; o < 16; o <<= 1) {
            sum += __shfl_xor_sync(0xffffffffu, sum, o);
            ssq += __shfl_xor_sync(0xffffffffu, ssq, o);
        }
        const float mu  = sum * (1.0f / 512.0f);
        const float var = ssq * (1.0f / 512.0f) - mu * mu;
        const float rs  = rsqrtf(var + 1e-5f);

        float dot = 0.f;
        #pragma unroll
        for (int j = 0; j < 16; j++) {
            const int h = 32 * j + 2 * ih;
            float hx, hy; unpack2(acc[a][j], hx, hy);
            const float yx = (hx - mu) * rs * sG[h]     + sB[h];
            const float yy = (hy - mu) * rs * sG[h + 1] + sB[h + 1];
            const float sx = yx * sigmoid_fast(yx);
            const float sy = yy * sigmoid_fast(yy);
            dot += sx * sW2g[h] + sy * sW2g[h + 1];
        }
        #pragma unroll
        for (int o = 1; o < 16; o <<= 1)
            dot += __shfl_xor_sync(0xffffffffu, dot, o);
        outv[a] = dot;
    }

    if (ih == 0) {
        const float bb = b2[0];
        float* o = out + (size_t)pr * Mn + m0 + 4 * im;
        #pragma unroll
        for (int a = 0; a < 4; a++) o[a] = outv[a] + bb;
    }
}

// ---------------------------------------------------------------------------
extern "C" void kernel_launch(void* const* d_in, const int* in_sizes, int n_in,
                              void* d_out, int out_size) {
    const float* track = (const float*)d_in[0];
    const float* det   = (const float*)d_in[1];
    const float* W1    = (const float*)d_in[2];
    const float* b1    = (const float*)d_in[3];
    const float* gamma = (const float*)d_in[4];
    const float* beta  = (const float*)d_in[5];
    const float* W2    = (const float*)d_in[6];
    const float* b2    = (const float*)d_in[7];
    float* out = (float*)d_out;

    cudaFuncSetAttribute(main_kernel,
                         cudaFuncAttributeMaxDynamicSharedMemorySize, SMEM_BYTES);

    prep_kernel<<<128, 256>>>(track, det, W1, b1);
    main_kernel<<<2 * Bn * Nn, 256, SMEM_BYTES>>>(W1, gamma, beta, W2, b2, out);
}

// round 5
// speedup vs baseline: 2.2434x; 2.2409x over previous
#include <cuda_runtime.h>
#include <cstdint>

#define Bn 8
#define Nn 128
#define Mn 128
#define En 256
#define Hn 512
#define NROWS 1024

__device__ float g_tn[NROWS*En];
__device__ float g_dn[NROWS*En];
__device__ float g_tA[NROWS*Hn];
__device__ float g_dD[NROWS*Hn];          // b1 folded in
__device__ float g_Wr[En*Hn];             // tf32-rounded W1c, [e][h]

// ---------------- helpers ----------------
__device__ __forceinline__ uint32_t smem_u32(const void* p) {
    uint32_t a;
    asm("{ .reg .u64 t; cvta.to.shared.u64 t, %1; cvt.u32.u64 %0, t; }" : "=r"(a) : "l"(p));
    return a;
}
__device__ __forceinline__ uint32_t to_tf32(float v) {
    uint32_t r; asm("cvt.rna.tf32.f32 %0, %1;" : "=r"(r) : "f"(v)); return r;
}
__device__ __forceinline__ float sigmoid_fast(float x) {
    float t; asm("tanh.approx.f32 %0, %1;" : "=f"(t) : "f"(x * 0.5f));
    return 0.5f * t + 0.5f;
}
__device__ __forceinline__ unsigned long long pack2(float lo, float hi) {
    unsigned long long r; asm("mov.b64 %0, {%1, %2};" : "=l"(r) : "f"(lo), "f"(hi)); return r;
}
__device__ __forceinline__ void unpack2(unsigned long long v, float& x, float& y) {
    asm("mov.b64 {%0, %1}, %2;" : "=f"(x), "=f"(y) : "l"(v));
}
__device__ __forceinline__ unsigned long long fma2(unsigned long long a,
                                                   unsigned long long b,
                                                   unsigned long long c) {
    unsigned long long d;
    asm("fma.rn.f32x2 %0, %1, %2, %3;" : "=l"(d) : "l"(a), "l"(b), "l"(c));
    return d;
}
__device__ __forceinline__ void cp16(uint32_t dst, const void* src) {
    asm volatile("cp.async.cg.shared.global [%0], [%1], 16;"
                 :: "r"(dst), "l"(src) : "memory");
}
#define CP_COMMIT() asm volatile("cp.async.commit_group;" ::: "memory")
#define CP_WAIT1()  asm volatile("cp.async.wait_group 1;" ::: "memory")
#define CP_WAIT0()  asm volatile("cp.async.wait_group 0;" ::: "memory")

__device__ __forceinline__ void mma8(float* c, const uint32_t* a,
                                     uint32_t b0, uint32_t b1) {
    asm volatile(
        "mma.sync.aligned.m16n8k8.row.col.f32.tf32.tf32.f32 "
        "{%0,%1,%2,%3}, {%4,%5,%6,%7}, {%8,%9}, {%0,%1,%2,%3};"
        : "+f"(c[0]), "+f"(c[1]), "+f"(c[2]), "+f"(c[3])
        : "r"(a[0]), "r"(a[1]), "r"(a[2]), "r"(a[3]), "r"(b0), "r"(b1));
}

// ---------------------------------------------------------------------------
// round W1c rows [512,768) of W1 into g_Wr with tf32 RNA rounding
// ---------------------------------------------------------------------------
__global__ __launch_bounds__(256) void round_kernel(const float* __restrict__ W1) {
    const int idx = (blockIdx.x * 256 + threadIdx.x) * 4;
    float4 v = *(const float4*)(W1 + (size_t)2 * En * Hn + idx);
    uint4 o;
    o.x = to_tf32(v.x); o.y = to_tf32(v.y);
    o.z = to_tf32(v.z); o.w = to_tf32(v.w);
    *(uint4*)(g_Wr + idx) = o;
}

// ---------------------------------------------------------------------------
// prep: L2-normalize rows; tA = t@W1a; dD = d@W1b + b1 (row-major, exact fp32)
// ---------------------------------------------------------------------------
__global__ __launch_bounds__(256) void prep_kernel(
    const float* __restrict__ track, const float* __restrict__ det,
    const float* __restrict__ W1, const float* __restrict__ b1)
{
    __shared__ float sX[16][En];
    __shared__ float sScale[16];
    const int tid = threadIdx.x;
    const int rb  = blockIdx.x * 16;
    const bool isT = (rb < NROWS);
    const float* src = isT ? (track + (size_t)rb * En)
                           : (det + (size_t)(rb - NROWS) * En);

    for (int idx = tid; idx < 16 * En; idx += 256)
        sX[idx >> 8][idx & 255] = src[idx];
    __syncthreads();
    {
        const int row = tid >> 4, k = tid & 15;
        float ss = 0.f;
        #pragma unroll
        for (int i = 0; i < 16; i++) { float v = sX[row][k + 16 * i]; ss += v * v; }
        #pragma unroll
        for (int o = 8; o; o >>= 1) ss += __shfl_xor_sync(0xffffffffu, ss, o);
        if (k == 0) sScale[row] = 1.0f / fmaxf(sqrtf(ss), 1e-12f);
    }
    __syncthreads();
    float* gnorm = isT ? (g_tn + (size_t)rb * En) : (g_dn + (size_t)(rb - NROWS) * En);
    for (int idx = tid; idx < 16 * En; idx += 256) {
        const int row = idx >> 8, e = idx & 255;
        float v = sX[row][e] * sScale[row];
        sX[row][e] = v;
        gnorm[idx] = v;
    }
    __syncthreads();

    const float* Wp = W1 + (isT ? 0 : (size_t)En * Hn);
    unsigned long long acc[16];
    #pragma unroll
    for (int r = 0; r < 16; r++) acc[r] = 0ull;
    #pragma unroll 4
    for (int e = 0; e < En; e++) {
        const unsigned long long w =
            *(const unsigned long long*)(Wp + (size_t)e * Hn + 2 * tid);
        #pragma unroll
        for (int r = 0; r < 16; r++)
            acc[r] = fma2(pack2(sX[r][e], sX[r][e]), w, acc[r]);
    }
    float bx = 0.f, by = 0.f;
    if (!isT) { bx = b1[2 * tid]; by = b1[2 * tid + 1]; }
    float* yout = isT ? (g_tA + (size_t)rb * Hn) : (g_dD + (size_t)(rb - NROWS) * Hn);
    #pragma unroll
    for (int r = 0; r < 16; r++) {
        float x, y; unpack2(acc[r], x, y);
        float2 v; v.x = x + bx; v.y = y + by;
        *(float2*)(yout + (size_t)r * Hn + 2 * tid) = v;
    }
}

// ---------------------------------------------------------------------------
// main: per-CTA (b, n, m-half) tf32 GEMM M=64,N=512,K=256 via mma.sync
//       + fused LN / SiLU / W2 epilogue. 256 threads, warps 2(m) x 4(h).
// ---------------------------------------------------------------------------
#define KC 16
#define APAD 260
#define BPAD 516
// float offsets in dynamic smem
#define F_A    0
#define F_B    (64*APAD)                   // 16640
#define F_TA   (F_B + 2*KC*BPAD)           // 33152
#define F_G    (F_TA + 512)
#define F_BT   (F_G + 512)
#define F_W2   (F_BT + 512)
#define F_SUM  (F_W2 + 512)                // [4][64]
#define F_SSQ  (F_SUM + 256)
#define F_DOT  (F_SSQ + 256)
#define F_MU   (F_DOT + 256)
#define F_RS   (F_MU + 64)
#define F_TN   (F_RS + 64)
#define SMEM_FLOATS (F_TN + 256)           // 36352
#define SMEM_BYTES  (SMEM_FLOATS * 4)      // 145408

__global__ __launch_bounds__(256, 1) void main_kernel(
    const float* __restrict__ gamma, const float* __restrict__ beta,
    const float* __restrict__ W2, const float* __restrict__ b2,
    float* __restrict__ out)
{
    extern __shared__ float sm[];
    float* sA  = sm + F_A;
    float* sB  = sm + F_B;
    float* sTA = sm + F_TA;
    float* sG  = sm + F_G;
    float* sBt = sm + F_BT;
    float* sW2 = sm + F_W2;
    float* sSum = sm + F_SUM;
    float* sSsq = sm + F_SSQ;
    float* sDot = sm + F_DOT;
    float* sMu  = sm + F_MU;
    float* sRs  = sm + F_RS;
    float* sTn  = sm + F_TN;

    const uint32_t sbase = smem_u32(sm);
    const uint32_t sbB   = sbase + F_B * 4;

    const int tid = threadIdx.x, lane = tid & 31, warp = tid >> 5;
    const int warpm = warp >> 2, warph = warp & 3;
    const int la3 = lane & 3, lq = lane >> 2;
    const int pr = blockIdx.x >> 1;           // b*128 + n
    const int m0 = (blockIdx.x & 1) * 64;
    const int b  = pr >> 7;

    // prefetch B chunks 0,1 immediately
    #pragma unroll
    for (int c = 0; c < 2; c++) {
        const float* src = g_Wr + (size_t)c * KC * Hn;
        const uint32_t dstb = sbB + (uint32_t)(c & 1) * (KC * BPAD * 4);
        #pragma unroll
        for (int g = 0; g < 8; g++) {
            const int gr = tid + g * 256;           // 0..2047
            const int row = gr >> 7, col = (gr & 127) * 4;
            cp16(dstb + (uint32_t)(row * BPAD + col) * 4, src + row * Hn + col);
        }
        CP_COMMIT();
    }

    // stage constants
    for (int i = tid; i < Hn; i += 256) {
        sTA[i] = g_tA[(size_t)pr * Hn + i];
        sG[i] = gamma[i]; sBt[i] = beta[i]; sW2[i] = W2[i];
    }
    for (int i = tid; i < En; i += 256) sTn[i] = g_tn[(size_t)pr * En + i];
    __syncthreads();

    // build A = tf32(|t - d|), [64][APAD]
    const float* dnb = g_dn + ((size_t)(b * Mn + m0)) * En;
    #pragma unroll
    for (int it = 0; it < 16; it++) {
        const int idx = tid + it * 256;          // 0..4095
        const int m = idx >> 6, e4 = (idx & 63) * 4;
        const float4 t = *(const float4*)(sTn + e4);
        const float4 d = *(const float4*)(dnb + (size_t)m * En + e4);
        uint4 o;
        o.x = to_tf32(fabsf(t.x - d.x));
        o.y = to_tf32(fabsf(t.y - d.y));
        o.z = to_tf32(fabsf(t.z - d.z));
        o.w = to_tf32(fabsf(t.w - d.w));
        *(uint4*)(sA + m * APAD + e4) = o;
    }

    float acc[2][16][4];
    #pragma unroll
    for (int i = 0; i < 2; i++)
        #pragma unroll
        for (int j = 0; j < 16; j++)
            #pragma unroll
            for (int q = 0; q < 4; q++) acc[i][j][q] = 0.f;

    // mainloop: 16 K-chunks, double-buffered cp.async
    for (int c = 0; c < 16; c++) {
        if (c < 15) { CP_WAIT1(); } else { CP_WAIT0(); }
        __syncthreads();
        const float* bbuf = sB + (c & 1) * (KC * BPAD);
        #pragma unroll
        for (int ks = 0; ks < 2; ks++) {
            const int kk = c * 16 + 8 * ks;
            uint32_t a[2][4];
            #pragma unroll
            for (int i = 0; i < 2; i++) {
                const int r = warpm * 32 + i * 16 + lq;
                const float* ap = sA + r * APAD + kk + la3;
                a[i][0] = __float_as_uint(ap[0]);
                a[i][1] = __float_as_uint(ap[8 * APAD]);
                a[i][2] = __float_as_uint(ap[4]);
                a[i][3] = __float_as_uint(ap[8 * APAD + 4]);
            }
            const float* b0p = bbuf + (8 * ks + la3) * BPAD + warph * 128 + lq;
            const float* b1p = b0p + 4 * BPAD;
            #pragma unroll
            for (int j = 0; j < 16; j++) {
                const uint32_t b0 = __float_as_uint(b0p[j * 8]);
                const uint32_t b1 = __float_as_uint(b1p[j * 8]);
                mma8(acc[0][j], a[0], b0, b1);
                mma8(acc[1][j], a[1], b0, b1);
            }
        }
        __syncthreads();
        if (c + 2 < 16) {
            const int cn = c + 2;
            const float* src = g_Wr + (size_t)cn * KC * Hn;
            const uint32_t dstb = sbB + (uint32_t)(cn & 1) * (KC * BPAD * 4);
            #pragma unroll
            for (int g = 0; g < 8; g++) {
                const int gr = tid + g * 256;
                const int row = gr >> 7, col = (gr & 127) * 4;
                cp16(dstb + (uint32_t)(row * BPAD + col) * 4, src + row * Hn + col);
            }
            CP_COMMIT();
        }
    }

    // ---- epilogue pass 1: add tA + dD, LN stats ----
    const float* dDb = g_dD + ((size_t)(b * Mn + m0)) * Hn;
    #pragma unroll
    for (int i = 0; i < 2; i++) {
        #pragma unroll
        for (int h2 = 0; h2 < 2; h2++) {
            const int ml = warpm * 32 + i * 16 + 8 * h2 + lq;
            const float* drow = dDb + (size_t)ml * Hn + warph * 128 + 2 * la3;
            float sum = 0.f, ssq = 0.f;
            #pragma unroll
            for (int j = 0; j < 16; j++) {
                const int h = warph * 128 + j * 8 + 2 * la3;
                const float2 dd = *(const float2*)(drow + j * 8);
                float v0 = acc[i][j][2 * h2]     + sTA[h]     + dd.x;
                float v1 = acc[i][j][2 * h2 + 1] + sTA[h + 1] + dd.y;
                acc[i][j][2 * h2] = v0; acc[i][j][2 * h2 + 1] = v1;
                sum += v0 + v1;
                ssq += v0 * v0 + v1 * v1;
            }
            sum += __shfl_xor_sync(0xffffffffu, sum, 1);
            sum += __shfl_xor_sync(0xffffffffu, sum, 2);
            ssq += __shfl_xor_sync(0xffffffffu, ssq, 1);
            ssq += __shfl_xor_sync(0xffffffffu, ssq, 2);
            if (la3 == 0) { sSum[warph * 64 + ml] = sum; sSsq[warph * 64 + ml] = ssq; }
        }
    }
    __syncthreads();
    if (tid < 64) {
        float s = sSum[tid] + sSum[64 + tid] + sSum[128 + tid] + sSum[192 + tid];
        float q = sSsq[tid] + sSsq[64 + tid] + sSsq[128 + tid] + sSsq[192 + tid];
        const float mu  = s * (1.f / 512.f);
        const float var = q * (1.f / 512.f) - mu * mu;
        sMu[tid] = mu;
        sRs[tid] = rsqrtf(var + 1e-5f);
    }
    __syncthreads();

    // ---- epilogue pass 2: LN, SiLU, W2 dot ----
    #pragma unroll
    for (int i = 0; i < 2; i++) {
        #pragma unroll
        for (int h2 = 0; h2 < 2; h2++) {
            const int ml = warpm * 32 + i * 16 + 8 * h2 + lq;
            const float mu = sMu[ml], rs = sRs[ml];
            float dot = 0.f;
            #pragma unroll
            for (int j = 0; j < 16; j++) {
                const int h = warph * 128 + j * 8 + 2 * la3;
                const float y0 = (acc[i][j][2 * h2]     - mu) * rs * sG[h]     + sBt[h];
                const float y1 = (acc[i][j][2 * h2 + 1] - mu) * rs * sG[h + 1] + sBt[h + 1];
                dot += (y0 * sigmoid_fast(y0)) * sW2[h];
                dot += (y1 * sigmoid_fast(y1)) * sW2[h + 1];
            }
            dot += __shfl_xor_sync(0xffffffffu, dot, 1);
            dot += __shfl_xor_sync(0xffffffffu, dot, 2);
            if (la3 == 0) sDot[warph * 64 + ml] = dot;
        }
    }
    __syncthreads();
    if (tid < 64) {
        const float d = sDot[tid] + sDot[64 + tid] + sDot[128 + tid]
                      + sDot[192 + tid] + b2[0];
        out[(size_t)pr * Mn + m0 + tid] = d;
    }
}

// ---------------------------------------------------------------------------
extern "C" void kernel_launch(void* const* d_in, const int* in_sizes, int n_in,
                              void* d_out, int out_size) {
    const float* track = (const float*)d_in[0];
    const float* det   = (const float*)d_in[1];
    const float* W1    = (const float*)d_in[2];
    const float* b1    = (const float*)d_in[3];
    const float* gamma = (const float*)d_in[4];
    const float* beta  = (const float*)d_in[5];
    const float* W2    = (const float*)d_in[6];
    const float* b2    = (const float*)d_in[7];
    float* out = (float*)d_out;

    cudaFuncSetAttribute(main_kernel,
                         cudaFuncAttributeMaxDynamicSharedMemorySize, SMEM_BYTES);

    round_kernel<<<256, 256>>>(W1);
    prep_kernel<<<128, 256>>>(track, det, W1, b1);
    main_kernel<<<2 * Bn * Nn, 256, SMEM_BYTES>>>(gamma, beta, W2, b2, out);
}

// round 6
// speedup vs baseline: 3.8863x; 1.7323x over previous
#include <cuda_runtime.h>
#include <cuda_fp16.h>
#include <cstdint>

#define Bn 8
#define Nn 128
#define Mn 128
#define En 256
#define Hn 512
#define NROWS 1024

__device__ float   g_tn[NROWS*En];
__device__ float   g_dn[NROWS*En];
__device__ float   g_tA[NROWS*Hn];
__device__ float   g_dD[NROWS*Hn];            // b1 folded in
__device__ __half2 g_Wh[(En/2)*Hn];           // W1c as half2 pairs along e: [p][h]

// ---------------- helpers ----------------
__device__ __forceinline__ uint32_t smem_u32(const void* p) {
    uint32_t a;
    asm("{ .reg .u64 t; cvta.to.shared.u64 t, %1; cvt.u32.u64 %0, t; }" : "=r"(a) : "l"(p));
    return a;
}
__device__ __forceinline__ float sigmoid_fast(float x) {
    float t; asm("tanh.approx.f32 %0, %1;" : "=f"(t) : "f"(x * 0.5f));
    return 0.5f * t + 0.5f;
}
__device__ __forceinline__ unsigned long long pack2(float lo, float hi) {
    unsigned long long r; asm("mov.b64 %0, {%1, %2};" : "=l"(r) : "f"(lo), "f"(hi)); return r;
}
__device__ __forceinline__ void unpack2(unsigned long long v, float& x, float& y) {
    asm("mov.b64 {%0, %1}, %2;" : "=f"(x), "=f"(y) : "l"(v));
}
__device__ __forceinline__ unsigned long long fma2(unsigned long long a,
                                                   unsigned long long b,
                                                   unsigned long long c) {
    unsigned long long d;
    asm("fma.rn.f32x2 %0, %1, %2, %3;" : "=l"(d) : "l"(a), "l"(b), "l"(c));
    return d;
}
__device__ __forceinline__ void cp16(uint32_t dst, const void* src) {
    asm volatile("cp.async.cg.shared.global [%0], [%1], 16;"
                 :: "r"(dst), "l"(src) : "memory");
}
#define CP_COMMIT() asm volatile("cp.async.commit_group;" ::: "memory")
#define CP_WAIT1()  asm volatile("cp.async.wait_group 1;" ::: "memory")
#define CP_WAIT0()  asm volatile("cp.async.wait_group 0;" ::: "memory")

// fp16 MMA, fp32 accumulate: D[16x8] += A[16x16] * B[16x8]
__device__ __forceinline__ void mma16(float* c, const uint32_t* a,
                                      uint32_t b0, uint32_t b1) {
    asm volatile(
        "mma.sync.aligned.m16n8k16.row.col.f32.f16.f16.f32 "
        "{%0,%1,%2,%3}, {%4,%5,%6,%7}, {%8,%9}, {%0,%1,%2,%3};"
        : "+f"(c[0]), "+f"(c[1]), "+f"(c[2]), "+f"(c[3])
        : "r"(a[0]), "r"(a[1]), "r"(a[2]), "r"(a[3]), "r"(b0), "r"(b1));
}

// ---------------------------------------------------------------------------
// Pack W1c (rows [512,768) of W1) into half2 e-pairs: g_Wh[p*Hn+h] =
// (W1c[2p][h], W1c[2p+1][h]). grid 256 x 256.
// ---------------------------------------------------------------------------
__global__ __launch_bounds__(256) void wh_kernel(const float* __restrict__ W1) {
    const int idx = blockIdx.x * 256 + threadIdx.x;   // 0..65535
    const int p = idx >> 9, h = idx & 511;
    const float w0 = W1[(size_t)(2 * En + 2 * p)     * Hn + h];
    const float w1 = W1[(size_t)(2 * En + 2 * p + 1) * Hn + h];
    g_Wh[idx] = __floats2half2_rn(w0, w1);
}

// ---------------------------------------------------------------------------
// prep: L2-normalize rows; tA = t@W1a; dD = d@W1b + b1 (row-major, exact fp32)
// ---------------------------------------------------------------------------
__global__ __launch_bounds__(256) void prep_kernel(
    const float* __restrict__ track, const float* __restrict__ det,
    const float* __restrict__ W1, const float* __restrict__ b1)
{
    __shared__ float sX[16][En];
    __shared__ float sScale[16];
    const int tid = threadIdx.x;
    const int rb  = blockIdx.x * 16;
    const bool isT = (rb < NROWS);
    const float* src = isT ? (track + (size_t)rb * En)
                           : (det + (size_t)(rb - NROWS) * En);

    for (int idx = tid; idx < 16 * En; idx += 256)
        sX[idx >> 8][idx & 255] = src[idx];
    __syncthreads();
    {
        const int row = tid >> 4, k = tid & 15;
        float ss = 0.f;
        #pragma unroll
        for (int i = 0; i < 16; i++) { float v = sX[row][k + 16 * i]; ss += v * v; }
        #pragma unroll
        for (int o = 8; o; o >>= 1) ss += __shfl_xor_sync(0xffffffffu, ss, o);
        if (k == 0) sScale[row] = 1.0f / fmaxf(sqrtf(ss), 1e-12f);
    }
    __syncthreads();
    float* gnorm = isT ? (g_tn + (size_t)rb * En) : (g_dn + (size_t)(rb - NROWS) * En);
    for (int idx = tid; idx < 16 * En; idx += 256) {
        const int row = idx >> 8, e = idx & 255;
        float v = sX[row][e] * sScale[row];
        sX[row][e] = v;
        gnorm[idx] = v;
    }
    __syncthreads();

    const float* Wp = W1 + (isT ? 0 : (size_t)En * Hn);
    unsigned long long acc[16];
    #pragma unroll
    for (int r = 0; r < 16; r++) acc[r] = 0ull;
    #pragma unroll 4
    for (int e = 0; e < En; e++) {
        const unsigned long long w =
            *(const unsigned long long*)(Wp + (size_t)e * Hn + 2 * tid);
        #pragma unroll
        for (int r = 0; r < 16; r++)
            acc[r] = fma2(pack2(sX[r][e], sX[r][e]), w, acc[r]);
    }
    float bx = 0.f, by = 0.f;
    if (!isT) { bx = b1[2 * tid]; by = b1[2 * tid + 1]; }
    float* yout = isT ? (g_tA + (size_t)rb * Hn) : (g_dD + (size_t)(rb - NROWS) * Hn);
    #pragma unroll
    for (int r = 0; r < 16; r++) {
        float x, y; unpack2(acc[r], x, y);
        float2 v; v.x = x + bx; v.y = y + by;
        *(float2*)(yout + (size_t)r * Hn + 2 * tid) = v;
    }
}

// ---------------------------------------------------------------------------
// main: per-CTA (b, n, m-half) fp16 GEMM M=64,N=512,K=256 (m16n8k16,
// fp32 accum) + fused LN / SiLU / W2 epilogue. warps 2(m) x 4(h).
// smem units below are 32-bit words.
// ---------------------------------------------------------------------------
#define AP 132                  // A row stride in half2 words (128 + 4 pad)
#define BP 520                  // B pair-row stride in half2 words (512 + 8 pad)
#define KC 32                   // e per chunk (16 pair-rows), 8 chunks
#define F_A    0
#define F_B    (64*AP)                     // 8448
#define F_TA   (F_B + 2*16*BP)             // 25088
#define F_G    (F_TA + 512)
#define F_BT   (F_G + 512)
#define F_W2   (F_BT + 512)
#define F_SUM  (F_W2 + 512)                // [4][64]
#define F_SSQ  (F_SUM + 256)
#define F_DOT  (F_SSQ + 256)
#define F_MU   (F_DOT + 256)
#define F_RS   (F_MU + 64)
#define F_TN   (F_RS + 64)
#define SMEM_WORDS (F_TN + 256)            // 28288
#define SMEM_BYTES (SMEM_WORDS * 4)        // 113152

__global__ __launch_bounds__(256, 1) void main_kernel(
    const float* __restrict__ gamma, const float* __restrict__ beta,
    const float* __restrict__ W2, const float* __restrict__ b2,
    float* __restrict__ out)
{
    extern __shared__ float sm[];
    uint32_t* sA  = (uint32_t*)sm + F_A;        // half2 words
    uint32_t* sB  = (uint32_t*)sm + F_B;        // half2 words
    float* sTA = sm + F_TA;
    float* sG  = sm + F_G;
    float* sBt = sm + F_BT;
    float* sW2 = sm + F_W2;
    float* sSum = sm + F_SUM;
    float* sSsq = sm + F_SSQ;
    float* sDot = sm + F_DOT;
    float* sMu  = sm + F_MU;
    float* sRs  = sm + F_RS;
    float* sTn  = sm + F_TN;

    const uint32_t sbB = smem_u32(sm) + F_B * 4;

    const int tid = threadIdx.x, lane = tid & 31, warp = tid >> 5;
    const int warpm = warp >> 2, warph = warp & 3;
    const int t4 = lane & 3, g8 = lane >> 2;
    const int pr = blockIdx.x >> 1;             // b*128 + n
    const int m0 = (blockIdx.x & 1) * 64;
    const int b  = pr >> 7;

    // prefetch B chunks 0,1 (16 pair-rows x 512 words each)
    #pragma unroll
    for (int c = 0; c < 2; c++) {
        const __half2* src = g_Wh + (size_t)c * 16 * Hn;
        const uint32_t dstb = sbB + (uint32_t)(c & 1) * (16 * BP * 4);
        #pragma unroll
        for (int g = 0; g < 8; g++) {
            const int gr = tid + g * 256;        // 0..2047
            const int row = gr >> 7, col = (gr & 127) * 4;
            cp16(dstb + (uint32_t)(row * BP + col) * 4, src + row * Hn + col);
        }
        CP_COMMIT();
    }

    // stage constants
    for (int i = tid; i < Hn; i += 256) {
        sTA[i] = g_tA[(size_t)pr * Hn + i];
        sG[i] = gamma[i]; sBt[i] = beta[i]; sW2[i] = W2[i];
    }
    for (int i = tid; i < En; i += 256) sTn[i] = g_tn[(size_t)pr * En + i];
    __syncthreads();

    // build A = half2(|t - d|) pairs along e, [64][AP]
    const float* dnb = g_dn + ((size_t)(b * Mn + m0)) * En;
    #pragma unroll
    for (int it = 0; it < 16; it++) {
        const int idx = tid + it * 256;          // 0..4095
        const int m = idx >> 6, q = idx & 63;    // q: float4 index, pairs 2q,2q+1
        const float4 t = *(const float4*)(sTn + 4 * q);
        const float4 d = *(const float4*)(dnb + (size_t)m * En + 4 * q);
        const __half2 h0 = __floats2half2_rn(fabsf(t.x - d.x), fabsf(t.y - d.y));
        const __half2 h1 = __floats2half2_rn(fabsf(t.z - d.z), fabsf(t.w - d.w));
        uint2 v;
        v.x = *(const uint32_t*)&h0;
        v.y = *(const uint32_t*)&h1;
        *(uint2*)(sA + m * AP + 2 * q) = v;
    }

    float acc[2][16][4];
    #pragma unroll
    for (int i = 0; i < 2; i++)
        #pragma unroll
        for (int j = 0; j < 16; j++)
            #pragma unroll
            for (int q = 0; q < 4; q++) acc[i][j][q] = 0.f;

    // mainloop: 8 chunks of 32 e, double-buffered cp.async
    for (int c = 0; c < 8; c++) {
        if (c < 7) { CP_WAIT1(); } else { CP_WAIT0(); }
        __syncthreads();
        const uint32_t* bbuf = sB + (c & 1) * (16 * BP);
        #pragma unroll
        for (int ks = 0; ks < 2; ks++) {
            const int pb = c * 16 + ks * 8;       // global pair base (kk/2)
            uint32_t a[2][4];
            #pragma unroll
            for (int i = 0; i < 2; i++) {
                const uint32_t* ap = sA + (warpm * 32 + i * 16 + g8) * AP + pb + t4;
                a[i][0] = ap[0];
                a[i][1] = ap[8 * AP];
                a[i][2] = ap[4];
                a[i][3] = ap[8 * AP + 4];
            }
            const uint32_t* b0p = bbuf + (ks * 8 + t4) * BP + warph * 128 + g8;
            const uint32_t* b1p = b0p + 4 * BP;
            #pragma unroll
            for (int j = 0; j < 16; j++) {
                const uint32_t b0 = b0p[j * 8];
                const uint32_t b1 = b1p[j * 8];
                mma16(acc[0][j], a[0], b0, b1);
                mma16(acc[1][j], a[1], b0, b1);
            }
        }
        __syncthreads();
        if (c + 2 < 8) {
            const int cn = c + 2;
            const __half2* src = g_Wh + (size_t)cn * 16 * Hn;
            const uint32_t dstb = sbB + (uint32_t)(cn & 1) * (16 * BP * 4);
            #pragma unroll
            for (int g = 0; g < 8; g++) {
                const int gr = tid + g * 256;
                const int row = gr >> 7, col = (gr & 127) * 4;
                cp16(dstb + (uint32_t)(row * BP + col) * 4, src + row * Hn + col);
            }
            CP_COMMIT();
        }
    }

    // ---- epilogue pass 1: add tA + dD, LN stats ----
    const float* dDb = g_dD + ((size_t)(b * Mn + m0)) * Hn;
    #pragma unroll
    for (int i = 0; i < 2; i++) {
        #pragma unroll
        for (int h2 = 0; h2 < 2; h2++) {
            const int ml = warpm * 32 + i * 16 + 8 * h2 + g8;
            const float* drow = dDb + (size_t)ml * Hn + warph * 128 + 2 * t4;
            float sum = 0.f, ssq = 0.f;
            #pragma unroll
            for (int j = 0; j < 16; j++) {
                const int h = warph * 128 + j * 8 + 2 * t4;
                const float2 dd = *(const float2*)(drow + j * 8);
                float v0 = acc[i][j][2 * h2]     + sTA[h]     + dd.x;
                float v1 = acc[i][j][2 * h2 + 1] + sTA[h + 1] + dd.y;
                acc[i][j][2 * h2] = v0; acc[i][j][2 * h2 + 1] = v1;
                sum += v0 + v1;
                ssq += v0 * v0 + v1 * v1;
            }
            sum += __shfl_xor_sync(0xffffffffu, sum, 1);
            sum += __shfl_xor_sync(0xffffffffu, sum, 2);
            ssq += __shfl_xor_sync(0xffffffffu, ssq, 1);
            ssq += __shfl_xor_sync(0xffffffffu, ssq, 2);
            if (t4 == 0) { sSum[warph * 64 + ml] = sum; sSsq[warph * 64 + ml] = ssq; }
        }
    }
    __syncthreads();
    if (tid < 64) {
        float s = sSum[tid] + sSum[64 + tid] + sSum[128 + tid] + sSum[192 + tid];
        float q = sSsq[tid] + sSsq[64 + tid] + sSsq[128 + tid] + sSsq[192 + tid];
        const float mu  = s * (1.f / 512.f);
        const float var = q * (1.f / 512.f) - mu * mu;
        sMu[tid] = mu;
        sRs[tid] = rsqrtf(var + 1e-5f);
    }
    __syncthreads();

    // ---- epilogue pass 2: LN, SiLU, W2 dot ----
    #pragma unroll
    for (int i = 0; i < 2; i++) {
        #pragma unroll
        for (int h2 = 0; h2 < 2; h2++) {
            const int ml = warpm * 32 + i * 16 + 8 * h2 + g8;
            const float mu = sMu[ml], rs = sRs[ml];
            float dot = 0.f;
            #pragma unroll
            for (int j = 0; j < 16; j++) {
                const int h = warph * 128 + j * 8 + 2 * t4;
                const float y0 = (acc[i][j][2 * h2]     - mu) * rs * sG[h]     + sBt[h];
                const float y1 = (acc[i][j][2 * h2 + 1] - mu) * rs * sG[h + 1] + sBt[h + 1];
                dot += (y0 * sigmoid_fast(y0)) * sW2[h];
                dot += (y1 * sigmoid_fast(y1)) * sW2[h + 1];
            }
            dot += __shfl_xor_sync(0xffffffffu, dot, 1);
            dot += __shfl_xor_sync(0xffffffffu, dot, 2);
            if (t4 == 0) sDot[warph * 64 + ml] = dot;
        }
    }
    __syncthreads();
    if (tid < 64) {
        const float d = sDot[tid] + sDot[64 + tid] + sDot[128 + tid]
                      + sDot[192 + tid] + b2[0];
        out[(size_t)pr * Mn + m0 + tid] = d;
    }
}

// ---------------------------------------------------------------------------
extern "C" void kernel_launch(void* const* d_in, const int* in_sizes, int n_in,
                              void* d_out, int out_size) {
    const float* track = (const float*)d_in[0];
    const float* det   = (const float*)d_in[1];
    const float* W1    = (const float*)d_in[2];
    const float* b1    = (const float*)d_in[3];
    const float* gamma = (const float*)d_in[4];
    const float* beta  = (const float*)d_in[5];
    const float* W2    = (const float*)d_in[6];
    const float* b2    = (const float*)d_in[7];
    float* out = (float*)d_out;

    cudaFuncSetAttribute(main_kernel,
                         cudaFuncAttributeMaxDynamicSharedMemorySize, SMEM_BYTES);

    wh_kernel<<<256, 256>>>(W1);
    prep_kernel<<<128, 256>>>(track, det, W1, b1);
    main_kernel<<<2 * Bn * Nn, 256, SMEM_BYTES>>>(gamma, beta, W2, b2, out);
}